// round 12
// baseline (speedup 1.0000x reference)
#include <cuda_runtime.h>
#include <math.h>
#include <stdint.h>

#define C_DIM   256
#define MED_DIM 128
#define HW_DIM  6400
#define B_DIM   16
#define K_OUT   128
#define P_PIX   32
#define NTHREADS 256
#define XSS     36          // xs row stride in floats (9 float4)

// smem layout in floats
#define OFF_XS   0                          // xs [256][36]          9216 f
#define OFF_XLT  9216                       // w1 double-buffer (2x4096) -> xl_t [32][256]
#define OFF_W    17408                      // w2 double-buffer (2x2048) | hb at +4096 | later prod
#define OFF_SIDX 25600                      // sidx2: 8192 bytes = 2048 f
#define SMEM_FLOATS 27648
#define SMEM_BYTES (SMEM_FLOATS * 4)        // 108 KB -> 2 CTAs/SM

// Pre-transposed weights (transpose only: NO arithmetic, keeps bits identical)
__device__ float d_w1t[C_DIM * MED_DIM];   // w1t[c][m]  = w1[m][c]
__device__ float d_w2t[MED_DIM * C_DIM];   // w2t[m][c'] = w2[c'][m]
__device__ float d_b1[MED_DIM];
__device__ float d_b2[C_DIM];

__global__ void prep_kernel(const float* __restrict__ w1, const float* __restrict__ b1,
                            const float* __restrict__ w2, const float* __restrict__ b2) {
    int bidx = blockIdx.x;      // 0..255
    int t = threadIdx.x;        // 0..255
    if (t < MED_DIM)  d_w1t[bidx * MED_DIM + t] = w1[t * C_DIM + bidx];
    if (bidx < MED_DIM) d_w2t[bidx * C_DIM + t] = w2[t * MED_DIM + bidx];
    if (bidx == 0 && t < MED_DIM) d_b1[t] = b1[t];
    if (bidx == 1) d_b2[t] = b2[t];
}

// ---- Bit-exact replica of XLA:CPU vectorized exp (Cephes / sse_mathfun lineage) ----
__device__ __forceinline__ float ref_expf(float v) {
    v = fminf(v, 88.3762626647950f);
    v = fmaxf(v, -88.3762626647949f);
    float fx = floorf(__fmaf_rn(v, 1.44269504088896341f, 0.5f));
    float x  = __fmaf_rn(fx, -0.693359375f, v);
    x = __fmaf_rn(fx, 2.12194440e-4f, x);
    float x2 = __fmul_rn(x, x);
    float y = 1.9875691500E-4f;
    y = __fmaf_rn(y, x, 1.3981999507E-3f);
    y = __fmaf_rn(y, x, 8.3334519073E-3f);
    y = __fmaf_rn(y, x, 4.1665795894E-2f);
    y = __fmaf_rn(y, x, 1.6666665459E-1f);
    y = __fmaf_rn(y, x, 5.0000001201E-1f);
    y = __fmaf_rn(y, x2, x);
    y = __fadd_rn(y, 1.0f);
    int n = (int)fx;
    float s = __int_as_float((n + 127) << 23);
    return __fmul_rn(y, s);
}

__device__ __forceinline__ float sigmoid_xla(float x) {
    float e = ref_expf(-x);
    return __fdiv_rn(1.0f, __fadd_rn(1.0f, e));
}

// ---- cp.async helpers ----
__device__ __forceinline__ void cp16(uint32_t dst, const void* src) {
    asm volatile("cp.async.ca.shared.global [%0], [%1], 16;" :: "r"(dst), "l"(src));
}
__device__ __forceinline__ void cp_commit() {
    asm volatile("cp.async.commit_group;" ::: "memory");
}
__device__ __forceinline__ void cp_wait0() {
    asm volatile("cp.async.wait_group 0;" ::: "memory");
}

// compare-exchange: after call, a holds the element that should come FIRST.
__device__ __forceinline__ void ce(unsigned long long& a, unsigned long long& b, bool up) {
    unsigned long long x = a, y = b;
    bool g = (x > y) == up;
    a = g ? x : y;
    b = g ? y : x;
}

extern __shared__ float smem[];

__global__ void __launch_bounds__(NTHREADS, 2)
csc_main_kernel(const float* __restrict__ x, float* __restrict__ out) {
    float* xs   = smem + OFF_XS;                 // [256][XSS]
    float* xl_t = smem + OFF_XLT;                // [32][256], after epilogue
    float* hb   = smem + OFF_W + 4096;           // [128][32] h tile
    float* prod = smem + OFF_W;                  // alias: [128][33] products (post-sort)
    unsigned char* sidx2 = (unsigned char*)(smem + OFF_SIDX);   // [32][256]

    float* w1b[2] = {smem + OFF_XLT, smem + OFF_XLT + 4096};    // 16KB chunks
    float* w2b[2] = {smem + OFF_W,   smem + OFF_W + 2048};      // 8KB chunks

    const uint32_t smem_u = (uint32_t)__cvta_generic_to_shared(smem);
    const uint32_t xs_u  = smem_u + OFF_XS * 4;
    const uint32_t w1b_u[2] = {smem_u + OFF_XLT * 4, smem_u + (OFF_XLT + 4096) * 4};
    const uint32_t w2b_u[2] = {smem_u + OFF_W * 4,   smem_u + (OFF_W + 2048) * 4};

    const int t   = threadIdx.x;
    const int bid = blockIdx.x;
    const int bb  = bid / 200;
    const int hw0 = (bid % 200) * P_PIX;

    const int tx = t & 7;       // pixel group: p = tx*4..+3
    const int ty = t >> 3;      // 0..31
    const int lane = t & 31;
    const int warp = t >> 5;

    // ---- upfront async loads: x tile + w1 chunk 0 ----
    const float* xg = x + ((size_t)bb * C_DIM) * HW_DIM + hw0;
#pragma unroll 2
    for (int i = t; i < C_DIM * 8; i += NTHREADS) {
        int c = i >> 3, seg = i & 7;
        cp16(xs_u + (c * 9 + seg) * 16, xg + (size_t)c * HW_DIM + seg * 4);
    }
#pragma unroll
    for (int i = t; i < 1024; i += NTHREADS)
        cp16(w1b_u[0] + i * 16, (const float4*)d_w1t + i);
    cp_commit();

    // ========== Stage A: h[m][p] = sum_c w1[m][c]*x[c][p]  (c ascending, FMA) ==========
    // w1 chunks: 32 c-rows x 128 m = 1024 float4, double-buffered; 8 chunks
    float a[4][4];
#pragma unroll
    for (int i = 0; i < 4; ++i)
#pragma unroll
        for (int j = 0; j < 4; ++j) a[i][j] = 0.f;

#pragma unroll 1
    for (int ch = 0; ch < 8; ++ch) {
        cp_wait0();
        __syncthreads();
        if (ch < 7) {
#pragma unroll
            for (int i = t; i < 1024; i += NTHREADS)
                cp16(w1b_u[(ch + 1) & 1] + i * 16, (const float4*)d_w1t + (ch + 1) * 1024 + i);
            cp_commit();
        } else {
            // prefetch w2 chunk 0 (8 m x 256 = 512 float4)
#pragma unroll
            for (int i = t; i < 512; i += NTHREADS)
                cp16(w2b_u[0] + i * 16, (const float4*)d_w2t + i);
            cp_commit();
        }
        const float4* wb = (const float4*)w1b[ch & 1];
#pragma unroll 4
        for (int cc = 0; cc < 32; ++cc) {
            float4 wv = wb[cc * 32 + ty];
            float4 xv = ((const float4*)xs)[(ch * 32 + cc) * 9 + tx];
            float wr[4] = {wv.x, wv.y, wv.z, wv.w};
            float xr[4] = {xv.x, xv.y, xv.z, xv.w};
#pragma unroll
            for (int i = 0; i < 4; ++i)
#pragma unroll
                for (int j = 0; j < 4; ++j)
                    a[i][j] = __fmaf_rn(wr[i], xr[j], a[i][j]);
        }
    }
    // hb lives in its own region -> safe to write now (readers gated by next barrier)
#pragma unroll
    for (int i = 0; i < 4; ++i) {
        int m = ty * 4 + i;
        float bs = d_b1[m];
#pragma unroll
        for (int j = 0; j < 4; ++j)
            hb[m * P_PIX + tx * 4 + j] = __fadd_rn(a[i][j], bs);
    }

    // ========== Stage B: x_[c'][p] = sum_m w2[c'][m]*h[m][p]  (m ascending, FMA) ==========
    // w2 chunks: 8 m x 256 c' = 512 float4, double-buffered; 16 chunks
    float b[8][4];
#pragma unroll
    for (int i = 0; i < 8; ++i)
#pragma unroll
        for (int j = 0; j < 4; ++j) b[i][j] = 0.f;

#pragma unroll 1
    for (int ch = 0; ch < 16; ++ch) {
        cp_wait0();
        __syncthreads();          // chunk data visible; hb visible (ch==0); buffer reuse safe
        if (ch < 15) {
#pragma unroll
            for (int i = t; i < 512; i += NTHREADS)
                cp16(w2b_u[(ch + 1) & 1] + i * 16, (const float4*)d_w2t + (ch + 1) * 512 + i);
            cp_commit();
        }
        const float4* wb = (const float4*)w2b[ch & 1];
#pragma unroll
        for (int mm = 0; mm < 8; ++mm) {
            float4 hv = ((const float4*)hb)[(ch * 8 + mm) * 8 + tx];
            float4 w0 = wb[mm * 64 + ty * 2];
            float4 w1v = wb[mm * 64 + ty * 2 + 1];
            float wr[8] = {w0.x, w0.y, w0.z, w0.w, w1v.x, w1v.y, w1v.z, w1v.w};
            float hr[4] = {hv.x, hv.y, hv.z, hv.w};
#pragma unroll
            for (int i = 0; i < 8; ++i)
#pragma unroll
                for (int j = 0; j < 4; ++j)
                    b[i][j] = __fmaf_rn(wr[i], hr[j], b[i][j]);
        }
    }
    __syncthreads();   // all warps done reading w1/w2 buffers & hb region

    // ---- epilogue: bias, write x_ transposed [p][c] (w1 buffers dead) ----
#pragma unroll
    for (int i = 0; i < 8; ++i) {
        int cp = ty * 8 + i;
        float bs = d_b2[cp];
#pragma unroll
        for (int j = 0; j < 4; ++j) {
            float v = __fadd_rn(b[i][j], bs);
            xl_t[(tx * 4 + j) * 256 + cp] = v;
        }
    }
    __syncthreads();

    // ========== register-resident bitonic sort: 2 pixels interleaved (ILP x2) ==========
    // element e = lane*8 + r ; key = (sigmoid_bits << 8) | (255 ^ c) ; key desc, c asc
#define CE2(i, j, up) { ce(P[i], P[j], up); ce(Q[i], Q[j], up); }
#pragma unroll 1
    for (int q = 0; q < 2; ++q) {
        int p0 = warp * 4 + q * 2;
        int p1 = p0 + 1;
        const float* r0 = xl_t + p0 * 256 + lane * 8;
        const float* r1 = xl_t + p1 * 256 + lane * 8;
        float4 a0 = *(const float4*)r0;
        float4 a1 = *(const float4*)(r0 + 4);
        float4 c0 = *(const float4*)r1;
        float4 c1 = *(const float4*)(r1 + 4);
        float va[8] = {a0.x, a0.y, a0.z, a0.w, a1.x, a1.y, a1.z, a1.w};
        float vb[8] = {c0.x, c0.y, c0.z, c0.w, c1.x, c1.y, c1.z, c1.w};
        unsigned long long P[8], Q[8];
#pragma unroll
        for (int r = 0; r < 8; ++r) {
            unsigned int ka = __float_as_uint(sigmoid_xla(va[r]));
            unsigned int kb = __float_as_uint(sigmoid_xla(vb[r]));
            unsigned long long tag = (unsigned long long)(0xFF ^ (lane * 8 + r));
            P[r] = ((unsigned long long)ka << 8) | tag;
            Q[r] = ((unsigned long long)kb << 8) | tag;
        }

        // k = 2: up = ((r&2)==0)
        CE2(0, 1, true);  CE2(2, 3, false);
        CE2(4, 5, true);  CE2(6, 7, false);
        // k = 4: up = ((r&4)==0)
        CE2(0, 2, true);  CE2(1, 3, true);
        CE2(4, 6, false); CE2(5, 7, false);
        CE2(0, 1, true);  CE2(2, 3, true);
        CE2(4, 5, false); CE2(6, 7, false);

        // k = 8..256: shfl levels (j>=8) + uniform-up local levels
#pragma unroll 1
        for (int k = 8; k <= 256; k <<= 1) {
#pragma unroll 1
            for (int j = k >> 1; j >= 8; j >>= 1) {
                int m = j >> 3;
                bool km = ((lane & (k >> 3)) == 0) == ((lane & m) == 0);
#pragma unroll
                for (int r = 0; r < 8; ++r) {
                    unsigned long long pv = __shfl_xor_sync(0xFFFFFFFFu, P[r], m);
                    unsigned long long qv = __shfl_xor_sync(0xFFFFFFFFu, Q[r], m);
                    P[r] = ((P[r] > pv) == km) ? P[r] : pv;
                    Q[r] = ((Q[r] > qv) == km) ? Q[r] : qv;
                }
            }
            bool upL = (((lane << 3) & k) == 0);
            CE2(0, 4, upL); CE2(1, 5, upL); CE2(2, 6, upL); CE2(3, 7, upL);
            CE2(0, 2, upL); CE2(1, 3, upL); CE2(4, 6, upL); CE2(5, 7, upL);
            CE2(0, 1, upL); CE2(2, 3, upL); CE2(4, 5, upL); CE2(6, 7, upL);
        }

        // element e holds rank e; emit channel bytes for both pixels
        unsigned long long wa = 0, wb2 = 0;
#pragma unroll
        for (int r = 0; r < 8; ++r) {
            wa  |= (unsigned long long)(0xFFu ^ (unsigned)(P[r] & 0xFFu)) << (8 * r);
            wb2 |= (unsigned long long)(0xFFu ^ (unsigned)(Q[r] & 0xFFu)) << (8 * r);
        }
        *(unsigned long long*)(sidx2 + p0 * 256 + lane * 8) = wa;
        *(unsigned long long*)(sidx2 + p1 * 256 + lane * 8) = wb2;
    }
#undef CE2
    __syncthreads();

    // ---- gather (rank-major lanes): prod[r][p] = x[c]*x_[c] ; stride-33 staging ----
#pragma unroll 4
    for (int it = 0; it < 16; ++it) {
        int task = t + NTHREADS * it;      // 32 px * 128 ranks
        int r = task & 127;
        int p = task >> 7;
        int c = sidx2[p * 256 + r];
        prod[r * 33 + p] = __fmul_rn(xs[c * XSS + p], xl_t[p * 256 + c]);
    }
    __syncthreads();

    // ---- write (pixel-major lanes): fully coalesced ----
#pragma unroll 4
    for (int it = 0; it < 16; ++it) {
        int task = t + NTHREADS * it;
        int p = task & 31;
        int rr = task >> 5;
        out[((size_t)(bb * K_OUT + rr)) * HW_DIM + hw0 + p] = prod[rr * 33 + p];
    }
}

extern "C" void kernel_launch(void* const* d_in, const int* in_sizes, int n_in,
                              void* d_out, int out_size) {
    const float* x  = (const float*)d_in[0];
    const float* w1 = (const float*)d_in[1];
    const float* b1 = (const float*)d_in[2];
    const float* w2 = (const float*)d_in[3];
    const float* b2 = (const float*)d_in[4];
    float* out = (float*)d_out;

    cudaFuncSetAttribute(csc_main_kernel,
                         cudaFuncAttributeMaxDynamicSharedMemorySize, SMEM_BYTES);
    prep_kernel<<<C_DIM, NTHREADS>>>(w1, b1, w2, b2);
    csc_main_kernel<<<(B_DIM * HW_DIM) / P_PIX, NTHREADS, SMEM_BYTES>>>(x, out);
}

// round 13
// speedup vs baseline: 1.1640x; 1.1640x over previous
#include <cuda_runtime.h>
#include <math.h>
#include <stdint.h>

#define C_DIM   256
#define MED_DIM 128
#define HW_DIM  6400
#define B_DIM   16
#define K_OUT   128
#define P_PIX   32
#define NTHREADS 256
#define XSS     36          // xs row stride in floats (9 float4)

// smem layout in floats
#define OFF_XS   0                          // xs [256][36]          9216 f
#define OFF_XLT  9216                       // w1 double-buffer (2x4096) -> xl_t [32][256]
#define OFF_W    17408                      // w2 double-buffer (2x2048) | hb at +4096 | later prod
#define OFF_SIDX 25600                      // sidx2: 8192 bytes = 2048 f
#define SMEM_FLOATS 27648
#define SMEM_BYTES (SMEM_FLOATS * 4)        // 108 KB -> 2 CTAs/SM

// Pre-transposed weights (transpose only: NO arithmetic, keeps bits identical)
__device__ float d_w1t[C_DIM * MED_DIM];   // w1t[c][m]  = w1[m][c]
__device__ float d_w2t[MED_DIM * C_DIM];   // w2t[m][c'] = w2[c'][m]
__device__ float d_b1[MED_DIM];
__device__ float d_b2[C_DIM];

__global__ void prep_kernel(const float* __restrict__ w1, const float* __restrict__ b1,
                            const float* __restrict__ w2, const float* __restrict__ b2) {
    int bidx = blockIdx.x;      // 0..255
    int t = threadIdx.x;        // 0..255
    if (t < MED_DIM)  d_w1t[bidx * MED_DIM + t] = w1[t * C_DIM + bidx];
    if (bidx < MED_DIM) d_w2t[bidx * C_DIM + t] = w2[t * MED_DIM + bidx];
    if (bidx == 0 && t < MED_DIM) d_b1[t] = b1[t];
    if (bidx == 1) d_b2[t] = b2[t];
}

// ---- Bit-exact replica of XLA:CPU vectorized exp (Cephes / sse_mathfun lineage) ----
__device__ __forceinline__ float ref_expf(float v) {
    v = fminf(v, 88.3762626647950f);
    v = fmaxf(v, -88.3762626647949f);
    float fx = floorf(__fmaf_rn(v, 1.44269504088896341f, 0.5f));
    float x  = __fmaf_rn(fx, -0.693359375f, v);
    x = __fmaf_rn(fx, 2.12194440e-4f, x);
    float x2 = __fmul_rn(x, x);
    float y = 1.9875691500E-4f;
    y = __fmaf_rn(y, x, 1.3981999507E-3f);
    y = __fmaf_rn(y, x, 8.3334519073E-3f);
    y = __fmaf_rn(y, x, 4.1665795894E-2f);
    y = __fmaf_rn(y, x, 1.6666665459E-1f);
    y = __fmaf_rn(y, x, 5.0000001201E-1f);
    y = __fmaf_rn(y, x2, x);
    y = __fadd_rn(y, 1.0f);
    int n = (int)fx;
    float s = __int_as_float((n + 127) << 23);
    return __fmul_rn(y, s);
}

__device__ __forceinline__ float sigmoid_xla(float x) {
    float e = ref_expf(-x);
    return __fdiv_rn(1.0f, __fadd_rn(1.0f, e));
}

// ---- cp.async helpers ----
__device__ __forceinline__ void cp16(uint32_t dst, const void* src) {
    asm volatile("cp.async.ca.shared.global [%0], [%1], 16;" :: "r"(dst), "l"(src));
}
__device__ __forceinline__ void cp_commit() {
    asm volatile("cp.async.commit_group;" ::: "memory");
}
__device__ __forceinline__ void cp_wait0() {
    asm volatile("cp.async.wait_group 0;" ::: "memory");
}

// compare-exchange: after call, a holds the element that should come FIRST.
__device__ __forceinline__ void ce(unsigned long long& a, unsigned long long& b, bool up) {
    unsigned long long x = a, y = b;
    bool g = (x > y) == up;
    a = g ? x : y;
    b = g ? y : x;
}

extern __shared__ float smem[];

__global__ void __launch_bounds__(NTHREADS, 2)
csc_main_kernel(const float* __restrict__ x, float* __restrict__ out) {
    float* xs   = smem + OFF_XS;                 // [256][XSS]
    float* xl_t = smem + OFF_XLT;                // [32][256], after epilogue
    float* hb   = smem + OFF_W + 4096;           // [128][32] h tile
    float* prod = smem + OFF_W;                  // alias: [128][33] products (post-sort)
    unsigned char* sidx2 = (unsigned char*)(smem + OFF_SIDX);   // [32][256]

    const uint32_t smem_u = (uint32_t)__cvta_generic_to_shared(smem);
    const uint32_t xs_u   = smem_u + OFF_XS * 4;
    const uint32_t w1b0_u = smem_u + OFF_XLT * 4;
    const uint32_t w1b1_u = smem_u + (OFF_XLT + 4096) * 4;
    const uint32_t w2b0_u = smem_u + OFF_W * 4;
    const uint32_t w2b1_u = smem_u + (OFF_W + 2048) * 4;

    const int t   = threadIdx.x;
    const int bid = blockIdx.x;
    const int bb  = bid / 200;
    const int hw0 = (bid % 200) * P_PIX;

    const int tx = t & 7;       // pixel group: p = tx*4..+3
    const int ty = t >> 3;      // 0..31
    const int lane = t & 31;
    const int warp = t >> 5;

    // ---- upfront async loads: x tile + w1 chunk 0 ----
    const float* xg = x + ((size_t)bb * C_DIM) * HW_DIM + hw0;
#pragma unroll 2
    for (int i = t; i < C_DIM * 8; i += NTHREADS) {
        int c = i >> 3, seg = i & 7;
        cp16(xs_u + (c * 9 + seg) * 16, xg + (size_t)c * HW_DIM + seg * 4);
    }
#pragma unroll
    for (int i = t; i < 1024; i += NTHREADS)
        cp16(w1b0_u + i * 16, (const float4*)d_w1t + i);
    cp_commit();

    // ========== Stage A: h[m][p] = sum_c w1[m][c]*x[c][p]  (c ascending, FMA) ==========
    // w1 chunks: 32 c-rows x 128 m = 1024 float4, double-buffered; 8 chunks
    float a[4][4];
#pragma unroll
    for (int i = 0; i < 4; ++i)
#pragma unroll
        for (int j = 0; j < 4; ++j) a[i][j] = 0.f;

#pragma unroll 1
    for (int ch = 0; ch < 8; ++ch) {
        cp_wait0();
        __syncthreads();
        if (ch < 7) {
            uint32_t dstu = ((ch & 1) ? w1b0_u : w1b1_u);
#pragma unroll
            for (int i = t; i < 1024; i += NTHREADS)
                cp16(dstu + i * 16, (const float4*)d_w1t + (ch + 1) * 1024 + i);
            cp_commit();
        } else {
            // prefetch w2 chunk 0 (8 m x 256 = 512 float4)
#pragma unroll
            for (int i = t; i < 512; i += NTHREADS)
                cp16(w2b0_u + i * 16, (const float4*)d_w2t + i);
            cp_commit();
        }
        const float4* wb = (const float4*)((ch & 1) ? (smem + OFF_XLT + 4096)
                                                    : (smem + OFF_XLT));
#pragma unroll 4
        for (int cc = 0; cc < 32; ++cc) {
            float4 wv = wb[cc * 32 + ty];
            float4 xv = ((const float4*)xs)[(ch * 32 + cc) * 9 + tx];
            float wr[4] = {wv.x, wv.y, wv.z, wv.w};
            float xr[4] = {xv.x, xv.y, xv.z, xv.w};
#pragma unroll
            for (int i = 0; i < 4; ++i)
#pragma unroll
                for (int j = 0; j < 4; ++j)
                    a[i][j] = __fmaf_rn(wr[i], xr[j], a[i][j]);
        }
    }
    // hb lives in its own region -> safe to write now (readers gated by next barrier)
#pragma unroll
    for (int i = 0; i < 4; ++i) {
        int m = ty * 4 + i;
        float bs = d_b1[m];
#pragma unroll
        for (int j = 0; j < 4; ++j)
            hb[m * P_PIX + tx * 4 + j] = __fadd_rn(a[i][j], bs);
    }

    // ========== Stage B: x_[c'][p] = sum_m w2[c'][m]*h[m][p]  (m ascending, FMA) ==========
    // w2 chunks: 8 m x 256 c' = 512 float4, double-buffered; 16 chunks
    float b[8][4];
#pragma unroll
    for (int i = 0; i < 8; ++i)
#pragma unroll
        for (int j = 0; j < 4; ++j) b[i][j] = 0.f;

#pragma unroll 1
    for (int ch = 0; ch < 16; ++ch) {
        cp_wait0();
        __syncthreads();          // chunk data visible; hb visible (ch==0); buffer reuse safe
        if (ch < 15) {
            uint32_t dstu = ((ch & 1) ? w2b0_u : w2b1_u);
#pragma unroll
            for (int i = t; i < 512; i += NTHREADS)
                cp16(dstu + i * 16, (const float4*)d_w2t + (ch + 1) * 512 + i);
            cp_commit();
        }
        const float4* wb = (const float4*)((ch & 1) ? (smem + OFF_W + 2048)
                                                    : (smem + OFF_W));
#pragma unroll
        for (int mm = 0; mm < 8; ++mm) {
            float4 hv = ((const float4*)hb)[(ch * 8 + mm) * 8 + tx];
            float4 w0 = wb[mm * 64 + ty * 2];
            float4 w1v = wb[mm * 64 + ty * 2 + 1];
            float wr[8] = {w0.x, w0.y, w0.z, w0.w, w1v.x, w1v.y, w1v.z, w1v.w};
            float hr[4] = {hv.x, hv.y, hv.z, hv.w};
#pragma unroll
            for (int i = 0; i < 8; ++i)
#pragma unroll
                for (int j = 0; j < 4; ++j)
                    b[i][j] = __fmaf_rn(wr[i], hr[j], b[i][j]);
        }
    }
    __syncthreads();   // all warps done reading w2 buffers & hb region

    // ---- epilogue: bias, write x_ transposed [p][c] (w1 buffers dead) ----
#pragma unroll
    for (int i = 0; i < 8; ++i) {
        int cp = ty * 8 + i;
        float bs = d_b2[cp];
#pragma unroll
        for (int j = 0; j < 4; ++j) {
            float v = __fadd_rn(b[i][j], bs);
            xl_t[(tx * 4 + j) * 256 + cp] = v;
        }
    }
    __syncthreads();

    // ========== register-resident bitonic sort: one warp per pixel (4 px/warp) ==========
    // element e = lane*8 + r ; key = (sigmoid_bits << 8) | (255 ^ c) ; key desc, c asc
#pragma unroll 1
    for (int q = 0; q < 4; ++q) {
        int p = warp * 4 + q;
        const float* row = xl_t + p * 256 + lane * 8;
        float4 v0 = *(const float4*)row;
        float4 v1 = *(const float4*)(row + 4);
        float vv[8] = {v0.x, v0.y, v0.z, v0.w, v1.x, v1.y, v1.z, v1.w};
        unsigned long long P[8];
#pragma unroll
        for (int r = 0; r < 8; ++r) {
            unsigned int kb = __float_as_uint(sigmoid_xla(vv[r]));
            P[r] = ((unsigned long long)kb << 8) |
                   (unsigned long long)(0xFF ^ (lane * 8 + r));
        }

        // k = 2: up = ((r&2)==0), compile-time
        ce(P[0], P[1], true);  ce(P[2], P[3], false);
        ce(P[4], P[5], true);  ce(P[6], P[7], false);
        // k = 4: up = ((r&4)==0), compile-time
        ce(P[0], P[2], true);  ce(P[1], P[3], true);
        ce(P[4], P[6], false); ce(P[5], P[7], false);
        ce(P[0], P[1], true);  ce(P[2], P[3], true);
        ce(P[4], P[5], false); ce(P[6], P[7], false);

        // k = 8..256: shfl levels (j>=8) + uniform-up local levels
#pragma unroll 1
        for (int k = 8; k <= 256; k <<= 1) {
#pragma unroll 1
            for (int j = k >> 1; j >= 8; j >>= 1) {
                int m = j >> 3;
                bool km = ((lane & (k >> 3)) == 0) == ((lane & m) == 0);
#pragma unroll
                for (int r = 0; r < 8; ++r) {
                    unsigned long long qv = __shfl_xor_sync(0xFFFFFFFFu, P[r], m);
                    P[r] = ((P[r] > qv) == km) ? P[r] : qv;
                }
            }
            bool upL = (((lane << 3) & k) == 0);
            ce(P[0], P[4], upL); ce(P[1], P[5], upL);
            ce(P[2], P[6], upL); ce(P[3], P[7], upL);
            ce(P[0], P[2], upL); ce(P[1], P[3], upL);
            ce(P[4], P[6], upL); ce(P[5], P[7], upL);
            ce(P[0], P[1], upL); ce(P[2], P[3], upL);
            ce(P[4], P[5], upL); ce(P[6], P[7], upL);
        }

        // element e now holds rank e; emit channel bytes, ranks lane*8..lane*8+7
        unsigned long long wbits = 0;
#pragma unroll
        for (int r = 0; r < 8; ++r)
            wbits |= (unsigned long long)(0xFFu ^ (unsigned)(P[r] & 0xFFu)) << (8 * r);
        *(unsigned long long*)(sidx2 + p * 256 + lane * 8) = wbits;
    }
    __syncthreads();

    // ---- gather (rank-major lanes): prod[r][p] = x[c]*x_[c] ; stride-33 staging ----
#pragma unroll 4
    for (int it = 0; it < 16; ++it) {
        int task = t + NTHREADS * it;      // 32 px * 128 ranks
        int r = task & 127;
        int p = task >> 7;
        int c = sidx2[p * 256 + r];
        prod[r * 33 + p] = __fmul_rn(xs[c * XSS + p], xl_t[p * 256 + c]);
    }
    __syncthreads();

    // ---- write (pixel-major lanes): fully coalesced ----
#pragma unroll 4
    for (int it = 0; it < 16; ++it) {
        int task = t + NTHREADS * it;
        int p = task & 31;
        int rr = task >> 5;
        out[((size_t)(bb * K_OUT + rr)) * HW_DIM + hw0 + p] = prod[rr * 33 + p];
    }
}

extern "C" void kernel_launch(void* const* d_in, const int* in_sizes, int n_in,
                              void* d_out, int out_size) {
    const float* x  = (const float*)d_in[0];
    const float* w1 = (const float*)d_in[1];
    const float* b1 = (const float*)d_in[2];
    const float* w2 = (const float*)d_in[3];
    const float* b2 = (const float*)d_in[4];
    float* out = (float*)d_out;

    cudaFuncSetAttribute(csc_main_kernel,
                         cudaFuncAttributeMaxDynamicSharedMemorySize, SMEM_BYTES);
    prep_kernel<<<C_DIM, NTHREADS>>>(w1, b1, w2, b2);
    csc_main_kernel<<<(B_DIM * HW_DIM) / P_PIX, NTHREADS, SMEM_BYTES>>>(x, out);
}

// round 14
// speedup vs baseline: 1.2108x; 1.0402x over previous
#include <cuda_runtime.h>
#include <math.h>
#include <stdint.h>

#define C_DIM   256
#define MED_DIM 128
#define HW_DIM  6400
#define B_DIM   16
#define K_OUT   128
#define P_PIX   32
#define NTHREADS 256
#define XSS     36          // xs row stride in floats (9 float4)

// smem layout in floats
#define OFF_XS   0          // xs [256][36]                                   9216 f
#define OFF_R2   9216       // A: w1 buf0 | B: w2-even(0..4096)+hb(4096..8192) | prod
#define OFF_R3   17408      // A: w1 buf1 | B: w2-odd(0..4096)               | xlt [32][256]
#define OFF_SIDX 25600      // sidx2: 8192 bytes = 2048 f
#define SMEM_FLOATS 27648
#define SMEM_BYTES (SMEM_FLOATS * 4)        // 108 KB -> 2 CTAs/SM

// Pre-transposed weights (transpose only: NO arithmetic, keeps bits identical)
__device__ float d_w1t[C_DIM * MED_DIM];   // w1t[c][m]  = w1[m][c]
__device__ float d_w2t[MED_DIM * C_DIM];   // w2t[m][c'] = w2[c'][m]
__device__ float d_b1[MED_DIM];
__device__ float d_b2[C_DIM];

__global__ void prep_kernel(const float* __restrict__ w1, const float* __restrict__ b1,
                            const float* __restrict__ w2, const float* __restrict__ b2) {
    int bidx = blockIdx.x;      // 0..255
    int t = threadIdx.x;        // 0..255
    if (t < MED_DIM)  d_w1t[bidx * MED_DIM + t] = w1[t * C_DIM + bidx];
    if (bidx < MED_DIM) d_w2t[bidx * C_DIM + t] = w2[t * MED_DIM + bidx];
    if (bidx == 0 && t < MED_DIM) d_b1[t] = b1[t];
    if (bidx == 1) d_b2[t] = b2[t];
}

// ---- Bit-exact replica of XLA:CPU vectorized exp (Cephes / sse_mathfun lineage) ----
__device__ __forceinline__ float ref_expf(float v) {
    v = fminf(v, 88.3762626647950f);
    v = fmaxf(v, -88.3762626647949f);
    float fx = floorf(__fmaf_rn(v, 1.44269504088896341f, 0.5f));
    float x  = __fmaf_rn(fx, -0.693359375f, v);
    x = __fmaf_rn(fx, 2.12194440e-4f, x);
    float x2 = __fmul_rn(x, x);
    float y = 1.9875691500E-4f;
    y = __fmaf_rn(y, x, 1.3981999507E-3f);
    y = __fmaf_rn(y, x, 8.3334519073E-3f);
    y = __fmaf_rn(y, x, 4.1665795894E-2f);
    y = __fmaf_rn(y, x, 1.6666665459E-1f);
    y = __fmaf_rn(y, x, 5.0000001201E-1f);
    y = __fmaf_rn(y, x2, x);
    y = __fadd_rn(y, 1.0f);
    int n = (int)fx;
    float s = __int_as_float((n + 127) << 23);
    return __fmul_rn(y, s);
}

__device__ __forceinline__ float sigmoid_xla(float x) {
    float e = ref_expf(-x);
    return __fdiv_rn(1.0f, __fadd_rn(1.0f, e));
}

// ---- cp.async helpers (.cg: L2-resident weights, skip L1) ----
__device__ __forceinline__ void cp16(uint32_t dst, const void* src) {
    asm volatile("cp.async.cg.shared.global [%0], [%1], 16;" :: "r"(dst), "l"(src));
}
__device__ __forceinline__ void cp_commit() {
    asm volatile("cp.async.commit_group;" ::: "memory");
}
__device__ __forceinline__ void cp_wait0() {
    asm volatile("cp.async.wait_group 0;" ::: "memory");
}

// compare-exchange: after call, a holds the element that should come FIRST.
__device__ __forceinline__ void ce(unsigned long long& a, unsigned long long& b, bool up) {
    unsigned long long x = a, y = b;
    bool g = (x > y) == up;
    a = g ? x : y;
    b = g ? y : x;
}

extern __shared__ float smem[];

__global__ void __launch_bounds__(NTHREADS, 2)
csc_main_kernel(const float* __restrict__ x, float* __restrict__ out) {
    float* xs   = smem + OFF_XS;                 // [256][XSS]
    float* hb   = smem + OFF_R2 + 4096;          // [128][32] h tile (stage B)
    float* xl_t = smem + OFF_R3;                 // [32][256] (post-GEMM)
    float* prod = smem + OFF_R2;                 // [128][33] (post-sort)
    unsigned char* sidx2 = (unsigned char*)(smem + OFF_SIDX);   // [32][256]

    const uint32_t smem_u = (uint32_t)__cvta_generic_to_shared(smem);
    const uint32_t xs_u = smem_u + OFF_XS * 4;
    const uint32_t r2_u = smem_u + OFF_R2 * 4;
    const uint32_t r3_u = smem_u + OFF_R3 * 4;

    const int t   = threadIdx.x;
    const int bid = blockIdx.x;
    const int bb  = bid / 200;
    const int hw0 = (bid % 200) * P_PIX;

    const int tx = t & 7;       // pixel group: p = tx*4..+3
    const int ty = t >> 3;      // 0..31
    const int lane = t & 31;
    const int warp = t >> 5;

    // ---- upfront async loads: x tile + w1 chunk 0 (64 c-rows -> R2) ----
    const float* xg = x + ((size_t)bb * C_DIM) * HW_DIM + hw0;
#pragma unroll 2
    for (int i = t; i < C_DIM * 8; i += NTHREADS) {
        int c = i >> 3, seg = i & 7;
        cp16(xs_u + (c * 9 + seg) * 16, xg + (size_t)c * HW_DIM + seg * 4);
    }
#pragma unroll
    for (int i = t; i < 2048; i += NTHREADS)
        cp16(r2_u + i * 16, (const float4*)d_w1t + i);
    cp_commit();

    // ========== Stage A: h[m][p] = sum_c w1[m][c]*x[c][p]  (c ascending, FMA) ==========
    // 4 chunks x 64 c-rows (2048 float4), ping-pong R2/R3
    float a[4][4];
#pragma unroll
    for (int i = 0; i < 4; ++i)
#pragma unroll
        for (int j = 0; j < 4; ++j) a[i][j] = 0.f;

#pragma unroll 1
    for (int ch = 0; ch < 4; ++ch) {
        cp_wait0();
        __syncthreads();
        if (ch < 3) {
            uint32_t dstu = (ch & 1) ? r2_u : r3_u;     // next chunk's buffer
#pragma unroll
            for (int i = t; i < 2048; i += NTHREADS)
                cp16(dstu + i * 16, (const float4*)d_w1t + (ch + 1) * 2048 + i);
            cp_commit();
        } else {
            // prefetch w2 chunk 0 (16 m-rows = 1024 float4) -> R2 lower (dead: held chunk 2)
#pragma unroll
            for (int i = t; i < 1024; i += NTHREADS)
                cp16(r2_u + i * 16, (const float4*)d_w2t + i);
            cp_commit();
        }
        const float4* wb = (const float4*)((ch & 1) ? (smem + OFF_R3) : (smem + OFF_R2));
#pragma unroll 4
        for (int cc = 0; cc < 64; ++cc) {
            float4 wv = wb[cc * 32 + ty];
            float4 xv = ((const float4*)xs)[(ch * 64 + cc) * 9 + tx];
            float wr[4] = {wv.x, wv.y, wv.z, wv.w};
            float xr[4] = {xv.x, xv.y, xv.z, xv.w};
#pragma unroll
            for (int i = 0; i < 4; ++i)
#pragma unroll
                for (int j = 0; j < 4; ++j)
                    a[i][j] = __fmaf_rn(wr[i], xr[j], a[i][j]);
        }
    }
    // hb -> R2 upper: R2-lower is w2c0 landing zone (disjoint); no warp reads R2-upper now.
    // Visibility to stage-B readers is published by B-ch0's __syncthreads.
#pragma unroll
    for (int i = 0; i < 4; ++i) {
        int m = ty * 4 + i;
        float bs = d_b1[m];
#pragma unroll
        for (int j = 0; j < 4; ++j)
            hb[m * P_PIX + tx * 4 + j] = __fadd_rn(a[i][j], bs);
    }

    // ========== Stage B: x_[c'][p] = sum_m w2[c'][m]*h[m][p]  (m ascending, FMA) ==========
    // 8 chunks x 16 m-rows (1024 float4), ping-pong R2-lower / R3-lower
    float b[8][4];
#pragma unroll
    for (int i = 0; i < 8; ++i)
#pragma unroll
        for (int j = 0; j < 4; ++j) b[i][j] = 0.f;

#pragma unroll 1
    for (int ch = 0; ch < 8; ++ch) {
        cp_wait0();
        __syncthreads();          // chunk visible; hb visible (ch==0); prev buffer reusable
        if (ch < 7) {
            uint32_t dstu = (ch & 1) ? r2_u : r3_u;     // next chunk's buffer (lower 4096)
#pragma unroll
            for (int i = t; i < 1024; i += NTHREADS)
                cp16(dstu + i * 16, (const float4*)d_w2t + (ch + 1) * 1024 + i);
            cp_commit();
        }
        const float4* wb = (const float4*)((ch & 1) ? (smem + OFF_R3) : (smem + OFF_R2));
#pragma unroll 4
        for (int mm = 0; mm < 16; ++mm) {
            float4 hv = ((const float4*)hb)[(ch * 16 + mm) * 8 + tx];
            float4 w0 = wb[mm * 64 + ty * 2];
            float4 w1v = wb[mm * 64 + ty * 2 + 1];
            float wr[8] = {w0.x, w0.y, w0.z, w0.w, w1v.x, w1v.y, w1v.z, w1v.w};
            float hr[4] = {hv.x, hv.y, hv.z, hv.w};
#pragma unroll
            for (int i = 0; i < 8; ++i)
#pragma unroll
                for (int j = 0; j < 4; ++j)
                    b[i][j] = __fmaf_rn(wr[i], hr[j], b[i][j]);
        }
    }
    __syncthreads();   // all warps done reading w2c7 (R3-lower) & hb

    // ---- epilogue: bias, write x_ transposed [p][c] into R3 ----
#pragma unroll
    for (int i = 0; i < 8; ++i) {
        int cp = ty * 8 + i;
        float bs = d_b2[cp];
#pragma unroll
        for (int j = 0; j < 4; ++j) {
            float v = __fadd_rn(b[i][j], bs);
            xl_t[(tx * 4 + j) * 256 + cp] = v;
        }
    }
    __syncthreads();

    // ========== register-resident bitonic sort: one warp per pixel (4 px/warp) ==========
    // element e = lane*8 + r ; key = (sigmoid_bits << 8) | (255 ^ c) ; key desc, c asc
#pragma unroll 1
    for (int q = 0; q < 4; ++q) {
        int p = warp * 4 + q;
        const float* row = xl_t + p * 256 + lane * 8;
        float4 v0 = *(const float4*)row;
        float4 v1 = *(const float4*)(row + 4);
        float vv[8] = {v0.x, v0.y, v0.z, v0.w, v1.x, v1.y, v1.z, v1.w};
        unsigned long long P[8];
#pragma unroll
        for (int r = 0; r < 8; ++r) {
            unsigned int kb = __float_as_uint(sigmoid_xla(vv[r]));
            P[r] = ((unsigned long long)kb << 8) |
                   (unsigned long long)(0xFF ^ (lane * 8 + r));
        }

        // k = 2: up = ((r&2)==0), compile-time
        ce(P[0], P[1], true);  ce(P[2], P[3], false);
        ce(P[4], P[5], true);  ce(P[6], P[7], false);
        // k = 4: up = ((r&4)==0), compile-time
        ce(P[0], P[2], true);  ce(P[1], P[3], true);
        ce(P[4], P[6], false); ce(P[5], P[7], false);
        ce(P[0], P[1], true);  ce(P[2], P[3], true);
        ce(P[4], P[5], false); ce(P[6], P[7], false);

        // k = 8..256: shfl levels (j>=8) + uniform-up local levels
#pragma unroll 1
        for (int k = 8; k <= 256; k <<= 1) {
#pragma unroll 1
            for (int j = k >> 1; j >= 8; j >>= 1) {
                int m = j >> 3;
                bool km = ((lane & (k >> 3)) == 0) == ((lane & m) == 0);
#pragma unroll
                for (int r = 0; r < 8; ++r) {
                    unsigned long long qv = __shfl_xor_sync(0xFFFFFFFFu, P[r], m);
                    P[r] = ((P[r] > qv) == km) ? P[r] : qv;
                }
            }
            bool upL = (((lane << 3) & k) == 0);
            ce(P[0], P[4], upL); ce(P[1], P[5], upL);
            ce(P[2], P[6], upL); ce(P[3], P[7], upL);
            ce(P[0], P[2], upL); ce(P[1], P[3], upL);
            ce(P[4], P[6], upL); ce(P[5], P[7], upL);
            ce(P[0], P[1], upL); ce(P[2], P[3], upL);
            ce(P[4], P[5], upL); ce(P[6], P[7], upL);
        }

        // element e now holds rank e; emit channel bytes, ranks lane*8..lane*8+7
        unsigned long long wbits = 0;
#pragma unroll
        for (int r = 0; r < 8; ++r)
            wbits |= (unsigned long long)(0xFFu ^ (unsigned)(P[r] & 0xFFu)) << (8 * r);
        *(unsigned long long*)(sidx2 + p * 256 + lane * 8) = wbits;
    }
    __syncthreads();

    // ---- gather (rank-major lanes): prod[r][p] = x[c]*x_[c] ; stride-33 staging ----
#pragma unroll 4
    for (int it = 0; it < 16; ++it) {
        int task = t + NTHREADS * it;      // 32 px * 128 ranks
        int r = task & 127;
        int p = task >> 7;
        int c = sidx2[p * 256 + r];
        prod[r * 33 + p] = __fmul_rn(xs[c * XSS + p], xl_t[p * 256 + c]);
    }
    __syncthreads();

    // ---- write (pixel-major lanes): fully coalesced ----
#pragma unroll 4
    for (int it = 0; it < 16; ++it) {
        int task = t + NTHREADS * it;
        int p = task & 31;
        int rr = task >> 5;
        out[((size_t)(bb * K_OUT + rr)) * HW_DIM + hw0 + p] = prod[rr * 33 + p];
    }
}

extern "C" void kernel_launch(void* const* d_in, const int* in_sizes, int n_in,
                              void* d_out, int out_size) {
    const float* x  = (const float*)d_in[0];
    const float* w1 = (const float*)d_in[1];
    const float* b1 = (const float*)d_in[2];
    const float* w2 = (const float*)d_in[3];
    const float* b2 = (const float*)d_in[4];
    float* out = (float*)d_out;

    cudaFuncSetAttribute(csc_main_kernel,
                         cudaFuncAttributeMaxDynamicSharedMemorySize, SMEM_BYTES);
    prep_kernel<<<C_DIM, NTHREADS>>>(w1, b1, w2, b2);
    csc_main_kernel<<<(B_DIM * HW_DIM) / P_PIX, NTHREADS, SMEM_BYTES>>>(x, out);
}

// round 15
// speedup vs baseline: 1.2192x; 1.0070x over previous
#include <cuda_runtime.h>
#include <math.h>
#include <stdint.h>

#define C_DIM   256
#define MED_DIM 128
#define HW_DIM  6400
#define B_DIM   16
#define K_OUT   128
#define P_PIX   32
#define NTHREADS 256
#define XSS     36          // xs row stride in floats (9 float4)

// smem layout in floats
#define OFF_XS   0          // xs [256][36]                                   9216 f
#define OFF_R2   9216       // A: w1 buf0 | B: w2-even(0..4096)+hb(4096..8192) | prod
#define OFF_R3   17408      // A: w1 buf1 | B: w2-odd(0..4096)               | xlt [32][256]
#define OFF_SIDX 25600      // sidx2: 8192 bytes = 2048 f
#define SMEM_FLOATS 27648
#define SMEM_BYTES (SMEM_FLOATS * 4)        // 108 KB -> 2 CTAs/SM

typedef unsigned long long u64;

// Pre-transposed weights (transpose only: NO arithmetic, keeps bits identical)
__device__ float d_w1t[C_DIM * MED_DIM];   // w1t[c][m]  = w1[m][c]
__device__ float d_w2t[MED_DIM * C_DIM];   // w2t[m][c'] = w2[c'][m]
__device__ float d_b1[MED_DIM];
__device__ float d_b2[C_DIM];

__global__ void prep_kernel(const float* __restrict__ w1, const float* __restrict__ b1,
                            const float* __restrict__ w2, const float* __restrict__ b2) {
    int bidx = blockIdx.x;      // 0..255
    int t = threadIdx.x;        // 0..255
    if (t < MED_DIM)  d_w1t[bidx * MED_DIM + t] = w1[t * C_DIM + bidx];
    if (bidx < MED_DIM) d_w2t[bidx * C_DIM + t] = w2[t * MED_DIM + bidx];
    if (bidx == 0 && t < MED_DIM) d_b1[t] = b1[t];
    if (bidx == 1) d_b2[t] = b2[t];
}

// ---- Bit-exact replica of XLA:CPU vectorized exp (Cephes / sse_mathfun lineage) ----
__device__ __forceinline__ float ref_expf(float v) {
    v = fminf(v, 88.3762626647950f);
    v = fmaxf(v, -88.3762626647949f);
    float fx = floorf(__fmaf_rn(v, 1.44269504088896341f, 0.5f));
    float x  = __fmaf_rn(fx, -0.693359375f, v);
    x = __fmaf_rn(fx, 2.12194440e-4f, x);
    float x2 = __fmul_rn(x, x);
    float y = 1.9875691500E-4f;
    y = __fmaf_rn(y, x, 1.3981999507E-3f);
    y = __fmaf_rn(y, x, 8.3334519073E-3f);
    y = __fmaf_rn(y, x, 4.1665795894E-2f);
    y = __fmaf_rn(y, x, 1.6666665459E-1f);
    y = __fmaf_rn(y, x, 5.0000001201E-1f);
    y = __fmaf_rn(y, x2, x);
    y = __fadd_rn(y, 1.0f);
    int n = (int)fx;
    float s = __int_as_float((n + 127) << 23);
    return __fmul_rn(y, s);
}

__device__ __forceinline__ float sigmoid_xla(float x) {
    float e = ref_expf(-x);
    return __fdiv_rn(1.0f, __fadd_rn(1.0f, e));
}

// ---- packed f32x2 helpers (each lane = independent IEEE-rn fp32 op; bit-exact) ----
__device__ __forceinline__ u64 bcast2(float w) {
    u64 o;
    asm("mov.b64 %0, {%1, %1};" : "=l"(o) : "r"(__float_as_uint(w)));
    return o;
}
__device__ __forceinline__ void fma2(u64& acc, u64 a, u64 b) {
    asm("fma.rn.f32x2 %0, %1, %2, %0;" : "+l"(acc) : "l"(a), "l"(b));
}
__device__ __forceinline__ u64 add2(u64 a, u64 b) {
    u64 o;
    asm("add.rn.f32x2 %0, %1, %2;" : "=l"(o) : "l"(a), "l"(b));
    return o;
}

// ---- cp.async helpers (.cg: L2-resident weights, skip L1) ----
__device__ __forceinline__ void cp16(uint32_t dst, const void* src) {
    asm volatile("cp.async.cg.shared.global [%0], [%1], 16;" :: "r"(dst), "l"(src));
}
__device__ __forceinline__ void cp_commit() {
    asm volatile("cp.async.commit_group;" ::: "memory");
}
__device__ __forceinline__ void cp_wait0() {
    asm volatile("cp.async.wait_group 0;" ::: "memory");
}

// compare-exchange: after call, a holds the element that should come FIRST.
__device__ __forceinline__ void ce(u64& a, u64& b, bool up) {
    u64 x = a, y = b;
    bool g = (x > y) == up;
    a = g ? x : y;
    b = g ? y : x;
}

extern __shared__ float smem[];

__global__ void __launch_bounds__(NTHREADS, 2)
csc_main_kernel(const float* __restrict__ x, float* __restrict__ out) {
    float* xs   = smem + OFF_XS;                 // [256][XSS]
    float* hb   = smem + OFF_R2 + 4096;          // [128][32] h tile (stage B)
    float* xl_t = smem + OFF_R3;                 // [32][256] (post-GEMM)
    float* prod = smem + OFF_R2;                 // [128][33] (post-sort)
    unsigned char* sidx2 = (unsigned char*)(smem + OFF_SIDX);   // [32][256]

    const uint32_t smem_u = (uint32_t)__cvta_generic_to_shared(smem);
    const uint32_t xs_u = smem_u + OFF_XS * 4;
    const uint32_t r2_u = smem_u + OFF_R2 * 4;
    const uint32_t r3_u = smem_u + OFF_R3 * 4;

    const int t   = threadIdx.x;
    const int bid = blockIdx.x;
    const int bb  = bid / 200;
    const int hw0 = (bid % 200) * P_PIX;

    const int tx = t & 7;       // pixel group: p = tx*4..+3
    const int ty = t >> 3;      // 0..31
    const int lane = t & 31;
    const int warp = t >> 5;

    // ---- upfront async loads: x tile + w1 chunk 0 (64 c-rows -> R2) ----
    const float* xg = x + ((size_t)bb * C_DIM) * HW_DIM + hw0;
#pragma unroll 2
    for (int i = t; i < C_DIM * 8; i += NTHREADS) {
        int c = i >> 3, seg = i & 7;
        cp16(xs_u + (c * 9 + seg) * 16, xg + (size_t)c * HW_DIM + seg * 4);
    }
#pragma unroll
    for (int i = t; i < 2048; i += NTHREADS)
        cp16(r2_u + i * 16, (const float4*)d_w1t + i);
    cp_commit();

    // ========== Stage A: h[m][p] = sum_c w1[m][c]*x[c][p]  (c ascending, FMA) ==========
    // packed f32x2 over pixel pairs (j0j1 | j2j3); per-chain bits identical to scalar
    // 4 chunks x 64 c-rows (2048 float4), ping-pong R2/R3
    u64 a2[4][2];
#pragma unroll
    for (int i = 0; i < 4; ++i) { a2[i][0] = 0ull; a2[i][1] = 0ull; }

#pragma unroll 1
    for (int ch = 0; ch < 4; ++ch) {
        cp_wait0();
        __syncthreads();
        if (ch < 3) {
            uint32_t dstu = (ch & 1) ? r2_u : r3_u;     // next chunk's buffer
#pragma unroll
            for (int i = t; i < 2048; i += NTHREADS)
                cp16(dstu + i * 16, (const float4*)d_w1t + (ch + 1) * 2048 + i);
            cp_commit();
        } else {
            // prefetch w2 chunk 0 (16 m-rows = 1024 float4) -> R2 lower (dead: held chunk 2)
#pragma unroll
            for (int i = t; i < 1024; i += NTHREADS)
                cp16(r2_u + i * 16, (const float4*)d_w2t + i);
            cp_commit();
        }
        const float4* wb = (const float4*)((ch & 1) ? (smem + OFF_R3) : (smem + OFF_R2));
#pragma unroll 4
        for (int cc = 0; cc < 64; ++cc) {
            float4 wv = wb[cc * 32 + ty];
            ulonglong2 xv = *(const ulonglong2*)&((const float4*)xs)[(ch * 64 + cc) * 9 + tx];
            u64 wp[4] = {bcast2(wv.x), bcast2(wv.y), bcast2(wv.z), bcast2(wv.w)};
#pragma unroll
            for (int i = 0; i < 4; ++i) {
                fma2(a2[i][0], wp[i], xv.x);
                fma2(a2[i][1], wp[i], xv.y);
            }
        }
    }
    // hb -> R2 upper (R2-lower is w2c0 landing zone, disjoint); published by B-ch0 barrier
#pragma unroll
    for (int i = 0; i < 4; ++i) {
        int m = ty * 4 + i;
        u64 bp = bcast2(d_b1[m]);
        ulonglong2 hv;
        hv.x = add2(a2[i][0], bp);
        hv.y = add2(a2[i][1], bp);
        *(ulonglong2*)(hb + m * P_PIX + tx * 4) = hv;
    }

    // ========== Stage B: x_[c'][p] = sum_m w2[c'][m]*h[m][p]  (m ascending, FMA) ==========
    // 8 chunks x 16 m-rows (1024 float4), ping-pong R2-lower / R3-lower
    u64 b2[8][2];
#pragma unroll
    for (int i = 0; i < 8; ++i) { b2[i][0] = 0ull; b2[i][1] = 0ull; }

#pragma unroll 1
    for (int ch = 0; ch < 8; ++ch) {
        cp_wait0();
        __syncthreads();          // chunk visible; hb visible (ch==0); prev buffer reusable
        if (ch < 7) {
            uint32_t dstu = (ch & 1) ? r2_u : r3_u;     // next chunk's buffer (lower 4096)
#pragma unroll
            for (int i = t; i < 1024; i += NTHREADS)
                cp16(dstu + i * 16, (const float4*)d_w2t + (ch + 1) * 1024 + i);
            cp_commit();
        }
        const float4* wb = (const float4*)((ch & 1) ? (smem + OFF_R3) : (smem + OFF_R2));
#pragma unroll 4
        for (int mm = 0; mm < 16; ++mm) {
            ulonglong2 hv = *(const ulonglong2*)&((const float4*)hb)[(ch * 16 + mm) * 8 + tx];
            float4 w0 = wb[mm * 64 + ty * 2];
            float4 w1v = wb[mm * 64 + ty * 2 + 1];
            u64 wp[8] = {bcast2(w0.x), bcast2(w0.y), bcast2(w0.z), bcast2(w0.w),
                         bcast2(w1v.x), bcast2(w1v.y), bcast2(w1v.z), bcast2(w1v.w)};
#pragma unroll
            for (int i = 0; i < 8; ++i) {
                fma2(b2[i][0], wp[i], hv.x);
                fma2(b2[i][1], wp[i], hv.y);
            }
        }
    }
    __syncthreads();   // all warps done reading w2c7 (R3-lower) & hb

    // ---- epilogue: bias, write x_ transposed [p][c] into R3 ----
#pragma unroll
    for (int i = 0; i < 8; ++i) {
        int cp = ty * 8 + i;
        u64 bp = bcast2(d_b2[cp]);
        u64 v01 = add2(b2[i][0], bp);
        u64 v23 = add2(b2[i][1], bp);
        xl_t[(tx * 4 + 0) * 256 + cp] = __uint_as_float((unsigned)(v01 & 0xFFFFFFFFull));
        xl_t[(tx * 4 + 1) * 256 + cp] = __uint_as_float((unsigned)(v01 >> 32));
        xl_t[(tx * 4 + 2) * 256 + cp] = __uint_as_float((unsigned)(v23 & 0xFFFFFFFFull));
        xl_t[(tx * 4 + 3) * 256 + cp] = __uint_as_float((unsigned)(v23 >> 32));
    }
    __syncthreads();

    // ========== register-resident bitonic sort: one warp per pixel (4 px/warp) ==========
    // element e = lane*8 + r ; key = (sigmoid_bits << 8) | (255 ^ c) ; key desc, c asc
#pragma unroll 1
    for (int q = 0; q < 4; ++q) {
        int p = warp * 4 + q;
        const float* row = xl_t + p * 256 + lane * 8;
        float4 v0 = *(const float4*)row;
        float4 v1 = *(const float4*)(row + 4);
        float vv[8] = {v0.x, v0.y, v0.z, v0.w, v1.x, v1.y, v1.z, v1.w};
        u64 P[8];
#pragma unroll
        for (int r = 0; r < 8; ++r) {
            unsigned int kb = __float_as_uint(sigmoid_xla(vv[r]));
            P[r] = ((u64)kb << 8) | (u64)(0xFF ^ (lane * 8 + r));
        }

        // k = 2: up = ((r&2)==0), compile-time
        ce(P[0], P[1], true);  ce(P[2], P[3], false);
        ce(P[4], P[5], true);  ce(P[6], P[7], false);
        // k = 4: up = ((r&4)==0), compile-time
        ce(P[0], P[2], true);  ce(P[1], P[3], true);
        ce(P[4], P[6], false); ce(P[5], P[7], false);
        ce(P[0], P[1], true);  ce(P[2], P[3], true);
        ce(P[4], P[5], false); ce(P[6], P[7], false);

        // k = 8..256: shfl levels (j>=8) + uniform-up local levels
#pragma unroll 1
        for (int k = 8; k <= 256; k <<= 1) {
#pragma unroll 1
            for (int j = k >> 1; j >= 8; j >>= 1) {
                int m = j >> 3;
                bool km = ((lane & (k >> 3)) == 0) == ((lane & m) == 0);
#pragma unroll
                for (int r = 0; r < 8; ++r) {
                    u64 qv = __shfl_xor_sync(0xFFFFFFFFu, P[r], m);
                    P[r] = ((P[r] > qv) == km) ? P[r] : qv;
                }
            }
            bool upL = (((lane << 3) & k) == 0);
            ce(P[0], P[4], upL); ce(P[1], P[5], upL);
            ce(P[2], P[6], upL); ce(P[3], P[7], upL);
            ce(P[0], P[2], upL); ce(P[1], P[3], upL);
            ce(P[4], P[6], upL); ce(P[5], P[7], upL);
            ce(P[0], P[1], upL); ce(P[2], P[3], upL);
            ce(P[4], P[5], upL); ce(P[6], P[7], upL);
        }

        // element e now holds rank e; emit channel bytes, ranks lane*8..lane*8+7
        u64 wbits = 0;
#pragma unroll
        for (int r = 0; r < 8; ++r)
            wbits |= (u64)(0xFFu ^ (unsigned)(P[r] & 0xFFu)) << (8 * r);
        *(u64*)(sidx2 + p * 256 + lane * 8) = wbits;
    }
    __syncthreads();

    // ---- gather (rank-major lanes): prod[r][p] = x[c]*x_[c] ; stride-33 staging ----
#pragma unroll 4
    for (int it = 0; it < 16; ++it) {
        int task = t + NTHREADS * it;      // 32 px * 128 ranks
        int r = task & 127;
        int p = task >> 7;
        int c = sidx2[p * 256 + r];
        prod[r * 33 + p] = __fmul_rn(xs[c * XSS + p], xl_t[p * 256 + c]);
    }
    __syncthreads();

    // ---- write (pixel-major lanes): fully coalesced ----
#pragma unroll 4
    for (int it = 0; it < 16; ++it) {
        int task = t + NTHREADS * it;
        int p = task & 31;
        int rr = task >> 5;
        out[((size_t)(bb * K_OUT + rr)) * HW_DIM + hw0 + p] = prod[rr * 33 + p];
    }
}

extern "C" void kernel_launch(void* const* d_in, const int* in_sizes, int n_in,
                              void* d_out, int out_size) {
    const float* x  = (const float*)d_in[0];
    const float* w1 = (const float*)d_in[1];
    const float* b1 = (const float*)d_in[2];
    const float* w2 = (const float*)d_in[3];
    const float* b2 = (const float*)d_in[4];
    float* out = (float*)d_out;

    cudaFuncSetAttribute(csc_main_kernel,
                         cudaFuncAttributeMaxDynamicSharedMemorySize, SMEM_BYTES);
    prep_kernel<<<C_DIM, NTHREADS>>>(w1, b1, w2, b2);
    csc_main_kernel<<<(B_DIM * HW_DIM) / P_PIX, NTHREADS, SMEM_BYTES>>>(x, out);
}

// round 16
// speedup vs baseline: 1.3988x; 1.1473x over previous
#include <cuda_runtime.h>
#include <math.h>
#include <stdint.h>

#define C_DIM   256
#define MED_DIM 128
#define HW_DIM  6400
#define B_DIM   16
#define K_OUT   128
#define P_PIX   16
#define NTHREADS 128
#define XSS     20          // xs row stride in floats (5 float4; 16B-aligned rows)

// smem layout in floats (54 KB total -> 4 CTAs/SM)
#define OFF_XS   0          // xs [256][20]                         5120 f
#define OFF_R2   5120       // A: w1 even | B: w2-even(0..2047)+hb(2048..4095) | prod[128][17]
#define OFF_R3   9216       // A: w1 odd  | B: w2-odd(0..2047)                | xlt [16][256]
#define OFF_SIDX 13312      // sidx: 16 px * 128 ranks = 2048 B = 512 f
#define SMEM_FLOATS 13824
#define SMEM_BYTES (SMEM_FLOATS * 4)

typedef unsigned long long u64;

// Pre-transposed weights (transpose only: NO arithmetic, keeps bits identical)
__device__ float d_w1t[C_DIM * MED_DIM];   // w1t[c][m]  = w1[m][c]
__device__ float d_w2t[MED_DIM * C_DIM];   // w2t[m][c'] = w2[c'][m]
__device__ float d_b1[MED_DIM];
__device__ float d_b2[C_DIM];

__global__ void prep_kernel(const float* __restrict__ w1, const float* __restrict__ b1,
                            const float* __restrict__ w2, const float* __restrict__ b2) {
    int bidx = blockIdx.x;      // 0..255
    int t = threadIdx.x;        // 0..255
    if (t < MED_DIM)  d_w1t[bidx * MED_DIM + t] = w1[t * C_DIM + bidx];
    if (bidx < MED_DIM) d_w2t[bidx * C_DIM + t] = w2[t * MED_DIM + bidx];
    if (bidx == 0 && t < MED_DIM) d_b1[t] = b1[t];
    if (bidx == 1) d_b2[t] = b2[t];
}

// ---- Bit-exact replica of XLA:CPU vectorized exp (Cephes / sse_mathfun lineage) ----
__device__ __forceinline__ float ref_expf(float v) {
    v = fminf(v, 88.3762626647950f);
    v = fmaxf(v, -88.3762626647949f);
    float fx = floorf(__fmaf_rn(v, 1.44269504088896341f, 0.5f));
    float x  = __fmaf_rn(fx, -0.693359375f, v);
    x = __fmaf_rn(fx, 2.12194440e-4f, x);
    float x2 = __fmul_rn(x, x);
    float y = 1.9875691500E-4f;
    y = __fmaf_rn(y, x, 1.3981999507E-3f);
    y = __fmaf_rn(y, x, 8.3334519073E-3f);
    y = __fmaf_rn(y, x, 4.1665795894E-2f);
    y = __fmaf_rn(y, x, 1.6666665459E-1f);
    y = __fmaf_rn(y, x, 5.0000001201E-1f);
    y = __fmaf_rn(y, x2, x);
    y = __fadd_rn(y, 1.0f);
    int n = (int)fx;
    float s = __int_as_float((n + 127) << 23);
    return __fmul_rn(y, s);
}

__device__ __forceinline__ float sigmoid_xla(float x) {
    float e = ref_expf(-x);
    return __fdiv_rn(1.0f, __fadd_rn(1.0f, e));
}

// ---- packed f32x2 helpers (each lane = independent IEEE-rn fp32 op; bit-exact) ----
__device__ __forceinline__ u64 bcast2(float w) {
    u64 o;
    asm("mov.b64 %0, {%1, %1};" : "=l"(o) : "r"(__float_as_uint(w)));
    return o;
}
__device__ __forceinline__ void fma2(u64& acc, u64 a, u64 b) {
    asm("fma.rn.f32x2 %0, %1, %2, %0;" : "+l"(acc) : "l"(a), "l"(b));
}
__device__ __forceinline__ u64 add2(u64 a, u64 b) {
    u64 o;
    asm("add.rn.f32x2 %0, %1, %2;" : "=l"(o) : "l"(a), "l"(b));
    return o;
}

// ---- cp.async helpers (.cg: L2-resident weights, skip L1) ----
__device__ __forceinline__ void cp16(uint32_t dst, const void* src) {
    asm volatile("cp.async.cg.shared.global [%0], [%1], 16;" :: "r"(dst), "l"(src));
}
__device__ __forceinline__ void cp_commit() {
    asm volatile("cp.async.commit_group;" ::: "memory");
}
__device__ __forceinline__ void cp_wait0() {
    asm volatile("cp.async.wait_group 0;" ::: "memory");
}

// compare-exchange: after call, a holds the element that should come FIRST.
__device__ __forceinline__ void ce(u64& a, u64& b, bool up) {
    u64 x = a, y = b;
    bool g = (x > y) == up;
    a = g ? x : y;
    b = g ? y : x;
}

extern __shared__ float smem[];

__global__ void __launch_bounds__(NTHREADS, 4)
csc_main_kernel(const float* __restrict__ x, float* __restrict__ out) {
    float* xs   = smem + OFF_XS;                 // [256][XSS]
    float* hb   = smem + OFF_R2 + 2048;          // [128][16] h tile (stage B)
    float* xl_t = smem + OFF_R3;                 // [16][256] (post-GEMM)
    float* prod = smem + OFF_R2;                 // [128][17] (post-sort)
    unsigned char* sidx2 = (unsigned char*)(smem + OFF_SIDX);   // [16][128]

    const uint32_t smem_u = (uint32_t)__cvta_generic_to_shared(smem);
    const uint32_t xs_u = smem_u + OFF_XS * 4;
    const uint32_t r2_u = smem_u + OFF_R2 * 4;
    const uint32_t r3_u = smem_u + OFF_R3 * 4;

    const int t   = threadIdx.x;
    const int bid = blockIdx.x;
    const int bb  = bid / 400;
    const int hw0 = (bid % 400) * P_PIX;

    const int tx = t & 3;       // pixel group: p = tx*4..+3
    const int ty = t >> 2;      // 0..31
    const int lane = t & 31;
    const int warp = t >> 5;    // 0..3

    // ---- upfront async loads: x tile (256x16) + w1 chunk 0 (32 c-rows -> R2) ----
    const float* xg = x + ((size_t)bb * C_DIM) * HW_DIM + hw0;
#pragma unroll 2
    for (int i = t; i < C_DIM * 4; i += NTHREADS) {
        int c = i >> 2, seg = i & 3;
        cp16(xs_u + (c * 5 + seg) * 16, xg + (size_t)c * HW_DIM + seg * 4);
    }
#pragma unroll
    for (int i = t; i < 1024; i += NTHREADS)
        cp16(r2_u + i * 16, (const float4*)d_w1t + i);
    cp_commit();

    // ========== Stage A: h[m][p] = sum_c w1[m][c]*x[c][p]  (c ascending, FMA) ==========
    // 8 chunks x 32 c-rows (1024 float4), ping-pong R2/R3; packed f32x2 pixel pairs
    u64 a2[4][2];
#pragma unroll
    for (int i = 0; i < 4; ++i) { a2[i][0] = 0ull; a2[i][1] = 0ull; }

#pragma unroll 1
    for (int ch = 0; ch < 8; ++ch) {
        cp_wait0();
        __syncthreads();
        if (ch < 7) {
            uint32_t dstu = (ch & 1) ? r2_u : r3_u;     // next chunk's buffer
#pragma unroll
            for (int i = t; i < 1024; i += NTHREADS)
                cp16(dstu + i * 16, (const float4*)d_w1t + (ch + 1) * 1024 + i);
            cp_commit();
        } else {
            // prefetch w2 chunk 0 (8 m-rows = 512 float4) -> R2 lower (dead)
#pragma unroll
            for (int i = t; i < 512; i += NTHREADS)
                cp16(r2_u + i * 16, (const float4*)d_w2t + i);
            cp_commit();
        }
        const float4* wb = (const float4*)((ch & 1) ? (smem + OFF_R3) : (smem + OFF_R2));
#pragma unroll 4
        for (int cc = 0; cc < 32; ++cc) {
            float4 wv = wb[cc * 32 + ty];
            ulonglong2 xv = *(const ulonglong2*)&((const float4*)xs)[(ch * 32 + cc) * 5 + tx];
            u64 wp[4] = {bcast2(wv.x), bcast2(wv.y), bcast2(wv.z), bcast2(wv.w)};
#pragma unroll
            for (int i = 0; i < 4; ++i) {
                fma2(a2[i][0], wp[i], xv.x);
                fma2(a2[i][1], wp[i], xv.y);
            }
        }
    }
    // hb -> R2 upper (R2-lower is w2c0 landing zone, disjoint); published by B-ch0 barrier
#pragma unroll
    for (int i = 0; i < 4; ++i) {
        int m = ty * 4 + i;
        u64 bp = bcast2(d_b1[m]);
        ulonglong2 hv;
        hv.x = add2(a2[i][0], bp);
        hv.y = add2(a2[i][1], bp);
        *(ulonglong2*)(hb + m * P_PIX + tx * 4) = hv;
    }

    // ========== Stage B: x_[c'][p] = sum_m w2[c'][m]*h[m][p]  (m ascending, FMA) ==========
    // 16 chunks x 8 m-rows (512 float4), ping-pong R2-lower / R3-lower
    u64 b2[8][2];
#pragma unroll
    for (int i = 0; i < 8; ++i) { b2[i][0] = 0ull; b2[i][1] = 0ull; }

#pragma unroll 1
    for (int ch = 0; ch < 16; ++ch) {
        cp_wait0();
        __syncthreads();          // chunk visible; hb visible (ch==0); prev buffer reusable
        if (ch < 15) {
            uint32_t dstu = (ch & 1) ? r2_u : r3_u;     // next chunk's buffer (lower 2048)
#pragma unroll
            for (int i = t; i < 512; i += NTHREADS)
                cp16(dstu + i * 16, (const float4*)d_w2t + (ch + 1) * 512 + i);
            cp_commit();
        }
        const float4* wb = (const float4*)((ch & 1) ? (smem + OFF_R3) : (smem + OFF_R2));
#pragma unroll 4
        for (int mm = 0; mm < 8; ++mm) {
            ulonglong2 hv = *(const ulonglong2*)&((const float4*)hb)[(ch * 8 + mm) * 4 + tx];
            float4 w0 = wb[mm * 64 + ty * 2];
            float4 w1v = wb[mm * 64 + ty * 2 + 1];
            u64 wp[8] = {bcast2(w0.x), bcast2(w0.y), bcast2(w0.z), bcast2(w0.w),
                         bcast2(w1v.x), bcast2(w1v.y), bcast2(w1v.z), bcast2(w1v.w)};
#pragma unroll
            for (int i = 0; i < 8; ++i) {
                fma2(b2[i][0], wp[i], hv.x);
                fma2(b2[i][1], wp[i], hv.y);
            }
        }
    }
    __syncthreads();   // all warps done reading w2c15 (R3-lower) & hb

    // ---- epilogue: bias, write x_ transposed [p][c] into R3 ----
#pragma unroll
    for (int i = 0; i < 8; ++i) {
        int cp = ty * 8 + i;
        u64 bp = bcast2(d_b2[cp]);
        u64 v01 = add2(b2[i][0], bp);
        u64 v23 = add2(b2[i][1], bp);
        xl_t[(tx * 4 + 0) * 256 + cp] = __uint_as_float((unsigned)(v01 & 0xFFFFFFFFull));
        xl_t[(tx * 4 + 1) * 256 + cp] = __uint_as_float((unsigned)(v01 >> 32));
        xl_t[(tx * 4 + 2) * 256 + cp] = __uint_as_float((unsigned)(v23 & 0xFFFFFFFFull));
        xl_t[(tx * 4 + 3) * 256 + cp] = __uint_as_float((unsigned)(v23 >> 32));
    }
    __syncthreads();

    // ========== register-resident bitonic sort: one warp per pixel (4 px/warp) ==========
    // element e = lane*8 + r ; key = (sigmoid_bits << 8) | (255 ^ c) ; key desc, c asc
#pragma unroll 1
    for (int q = 0; q < 4; ++q) {
        int p = warp * 4 + q;
        const float* row = xl_t + p * 256 + lane * 8;
        float4 v0 = *(const float4*)row;
        float4 v1 = *(const float4*)(row + 4);
        float vv[8] = {v0.x, v0.y, v0.z, v0.w, v1.x, v1.y, v1.z, v1.w};
        u64 P[8];
#pragma unroll
        for (int r = 0; r < 8; ++r) {
            unsigned int kb = __float_as_uint(sigmoid_xla(vv[r]));
            P[r] = ((u64)kb << 8) | (u64)(0xFF ^ (lane * 8 + r));
        }

        // k = 2: up = ((r&2)==0), compile-time
        ce(P[0], P[1], true);  ce(P[2], P[3], false);
        ce(P[4], P[5], true);  ce(P[6], P[7], false);
        // k = 4: up = ((r&4)==0), compile-time
        ce(P[0], P[2], true);  ce(P[1], P[3], true);
        ce(P[4], P[6], false); ce(P[5], P[7], false);
        ce(P[0], P[1], true);  ce(P[2], P[3], true);
        ce(P[4], P[5], false); ce(P[6], P[7], false);

        // k = 8..256: shfl levels (j>=8) + uniform-up local levels
#pragma unroll 1
        for (int k = 8; k <= 256; k <<= 1) {
#pragma unroll 1
            for (int j = k >> 1; j >= 8; j >>= 1) {
                int m = j >> 3;
                bool km = ((lane & (k >> 3)) == 0) == ((lane & m) == 0);
#pragma unroll
                for (int r = 0; r < 8; ++r) {
                    u64 qv = __shfl_xor_sync(0xFFFFFFFFu, P[r], m);
                    P[r] = ((P[r] > qv) == km) ? P[r] : qv;
                }
            }
            bool upL = (((lane << 3) & k) == 0);
            ce(P[0], P[4], upL); ce(P[1], P[5], upL);
            ce(P[2], P[6], upL); ce(P[3], P[7], upL);
            ce(P[0], P[2], upL); ce(P[1], P[3], upL);
            ce(P[4], P[6], upL); ce(P[5], P[7], upL);
            ce(P[0], P[1], upL); ce(P[2], P[3], upL);
            ce(P[4], P[5], upL); ce(P[6], P[7], upL);
        }

        // element e holds rank e; only ranks 0..127 are needed (lanes 0..15)
        if (lane < 16) {
            u64 wbits = 0;
#pragma unroll
            for (int r = 0; r < 8; ++r)
                wbits |= (u64)(0xFFu ^ (unsigned)(P[r] & 0xFFu)) << (8 * r);
            *(u64*)(sidx2 + p * 128 + lane * 8) = wbits;
        }
    }
    __syncthreads();

    // ---- gather (rank-major lanes): prod[r][p] = x[c]*x_[c] ; stride-17 staging ----
#pragma unroll 4
    for (int it = 0; it < 16; ++it) {
        int task = t + NTHREADS * it;      // 16 px * 128 ranks
        int r = task & 127;
        int p = task >> 7;
        int c = sidx2[p * 128 + r];
        prod[r * 17 + p] = __fmul_rn(xs[c * XSS + p], xl_t[p * 256 + c]);
    }
    __syncthreads();

    // ---- write (pixel-major lanes): coalesced 64B segments ----
#pragma unroll 4
    for (int it = 0; it < 16; ++it) {
        int task = t + NTHREADS * it;
        int p = task & 15;
        int rr = task >> 4;
        out[((size_t)(bb * K_OUT + rr)) * HW_DIM + hw0 + p] = prod[rr * 17 + p];
    }
}

extern "C" void kernel_launch(void* const* d_in, const int* in_sizes, int n_in,
                              void* d_out, int out_size) {
    const float* x  = (const float*)d_in[0];
    const float* w1 = (const float*)d_in[1];
    const float* b1 = (const float*)d_in[2];
    const float* w2 = (const float*)d_in[3];
    const float* b2 = (const float*)d_in[4];
    float* out = (float*)d_out;

    cudaFuncSetAttribute(csc_main_kernel,
                         cudaFuncAttributeMaxDynamicSharedMemorySize, SMEM_BYTES);
    prep_kernel<<<C_DIM, 256>>>(w1, b1, w2, b2);
    csc_main_kernel<<<(B_DIM * HW_DIM) / P_PIX, NTHREADS, SMEM_BYTES>>>(x, out);
}